// round 16
// baseline (speedup 1.0000x reference)
#include <cuda_runtime.h>
#include <cuda_bf16.h>
#include <math.h>

#define BB 16
#define DD 256
#define TT 4096
#define NN (BB*TT)      // 65536 rows
#define KK 1024         // codes
#define ROWS 64         // rows per CTA
#define NTH 256
#define NCHUNK 64       // codes per pass
#define NPASS (KK/NCHUNK)   // 16
#define KSTEPS (DD/16)  // 16
#define MARGIN 1.5e-4f

#define OUT_LOSS ((size_t)NN*DD)
#define OUT_PERP (OUT_LOSS+1)
#define OUT_IDX  (OUT_PERP+1)

// padded smem row: 256 bf16 + 8 pad = 528 B (132 words; 132%32=4 -> conflict-free ldmatrix)
#define RSTR 528
#define SM_WN    0                      // 1024 floats
#define SM_A_HI  4096                   // 64*528 = 33792
#define SM_A_LO  (SM_A_HI + 33792)      // 37888
#define SM_B     (SM_A_LO + 33792)      // 71680: 64*528 = 33792
#define SM_MS    (SM_B + 33792)         // 105472: float[64][2]
#define SM_MI    (SM_MS + 512)
#define SM_MSS   (SM_MI + 512)
#define SM_IDX   (SM_MSS + 512)         // int[64]
#define SM_RBUF  (SM_IDX + 256)         // float[8]
#define SM_TOTAL (SM_RBUF + 32)         // 107296

// refine smem: stride 260 floats (1040 B, 16B-aligned, LDS.128 conflict-free)
#define RFS 260
#define RF_TOTAL (64 * RFS * 4 + 128)   // xs[32][260] + wch[32][260] + rows[32]

typedef unsigned int u32;

__device__ float  g_wnorm[KK];
__device__ float  g_xnorm[NN];
__device__ int    g_counts[KK];
__device__ double g_acc;
__device__ int    g_bestI[NN];
__device__ int    g_amb[NN];
__device__ int    g_namb;
__device__ __nv_bfloat16 g_whi[KK * DD];   // plain [k][d]

__device__ __forceinline__ u32 smem_u32(const void* p) {
    u32 a; asm("{ .reg .u64 t; cvta.to.shared.u64 t, %1; cvt.u32.u64 %0, t; }" : "=r"(a) : "l"(p));
    return a;
}
__device__ __forceinline__ void ldsm4(u32& r0, u32& r1, u32& r2, u32& r3, u32 addr) {
    asm volatile("ldmatrix.sync.aligned.m8n8.x4.shared.b16 {%0,%1,%2,%3}, [%4];"
        : "=r"(r0), "=r"(r1), "=r"(r2), "=r"(r3) : "r"(addr));
}
__device__ __forceinline__ void mma_bf16(float* c, u32 a0, u32 a1, u32 a2, u32 a3, u32 b0, u32 b1) {
    asm volatile("mma.sync.aligned.m16n8k16.row.col.f32.bf16.bf16.f32 "
        "{%0,%1,%2,%3}, {%4,%5,%6,%7}, {%8,%9}, {%0,%1,%2,%3};"
        : "+f"(c[0]), "+f"(c[1]), "+f"(c[2]), "+f"(c[3])
        : "r"(a0), "r"(a1), "r"(a2), "r"(a3), "r"(b0), "r"(b1));
}
__device__ __forceinline__ void upd(float s, int j, float& bs, int& bi, float& ss) {
    if (s < bs) { ss = bs; bs = s; bi = j; }
    else if (s < ss) ss = s;
}
__device__ __forceinline__ void qmerge(float& bs, int& bi, float& ss, int m) {
    float obs = __shfl_xor_sync(0xffffffffu, bs, m);
    int   obi = __shfl_xor_sync(0xffffffffu, bi, m);
    float oss = __shfl_xor_sync(0xffffffffu, ss, m);
    if (obs < bs || (obs == bs && obi < bi)) { ss = fminf(bs, oss); bs = obs; bi = obi; }
    else ss = fminf(ss, fminf(obs, oss));
}

// ---------------- prep (fused): wnorm + bf16 codebook + zero scratch -------
__global__ __launch_bounds__(256) void vq_prep(const float* __restrict__ w) {
    int gt   = blockIdx.x * blockDim.x + threadIdx.x;
    int k    = gt >> 5, lane = gt & 31;            // warp per code, 128 blocks
    const float4* wr = (const float4*)(w + (size_t)k * DD);
    float4 v0 = __ldg(&wr[lane]);                  // 64 float4 per row: lane, lane+32
    float4 v1 = __ldg(&wr[lane + 32]);
    float s = 0.f;
    s = __fmaf_rn(v0.x, v0.x, s); s = __fmaf_rn(v0.y, v0.y, s);
    s = __fmaf_rn(v0.z, v0.z, s); s = __fmaf_rn(v0.w, v0.w, s);
    s = __fmaf_rn(v1.x, v1.x, s); s = __fmaf_rn(v1.y, v1.y, s);
    s = __fmaf_rn(v1.z, v1.z, s); s = __fmaf_rn(v1.w, v1.w, s);
    #pragma unroll
    for (int o = 16; o; o >>= 1) s = __fadd_rn(s, __shfl_xor_sync(0xffffffffu, s, o));
    if (lane == 0) g_wnorm[k] = s;
    u32 p0 = (u32)__bfloat16_as_ushort(__float2bfloat16(v0.x))
           | ((u32)__bfloat16_as_ushort(__float2bfloat16(v0.y)) << 16);
    u32 p1 = (u32)__bfloat16_as_ushort(__float2bfloat16(v0.z))
           | ((u32)__bfloat16_as_ushort(__float2bfloat16(v0.w)) << 16);
    u32 p2 = (u32)__bfloat16_as_ushort(__float2bfloat16(v1.x))
           | ((u32)__bfloat16_as_ushort(__float2bfloat16(v1.y)) << 16);
    u32 p3 = (u32)__bfloat16_as_ushort(__float2bfloat16(v1.z))
           | ((u32)__bfloat16_as_ushort(__float2bfloat16(v1.w)) << 16);
    uint2* dst = (uint2*)g_whi;
    dst[(size_t)k * 64 + lane]      = make_uint2(p0, p1);
    dst[(size_t)k * 64 + lane + 32] = make_uint2(p2, p3);
    if (gt < KK) g_counts[gt] = 0;
    if (gt == 0) { g_acc = 0.0; g_namb = 0; }
}

// ---------------- xnorm: per-row sum(x^2), GPU warp-reduce order ----------
__global__ __launch_bounds__(256) void vq_xnorm(const float* __restrict__ x) {
    int r = blockIdx.x * blockDim.x + threadIdx.x;
    int b = r >> 12, t = r & 4095;
    const float* xp = x + (size_t)b * (DD * TT) + t;
    float pA[32];
    #pragma unroll
    for (int l = 0; l < 32; l++) pA[l] = 0.f;
    #pragma unroll 1
    for (int i = 0; i < 8; i++) {
        #pragma unroll
        for (int l = 0; l < 32; l++) {
            float v = __ldg(&xp[(size_t)(i * 32 + l) * TT]);
            pA[l] = __fadd_rn(pA[l], __fmul_rn(v, v));
        }
    }
    #pragma unroll
    for (int l = 0; l < 16; l++) pA[l] = __fadd_rn(pA[l], pA[l + 16]);
    #pragma unroll
    for (int l = 0; l < 8; l++)  pA[l] = __fadd_rn(pA[l], pA[l + 8]);
    #pragma unroll
    for (int l = 0; l < 4; l++)  pA[l] = __fadd_rn(pA[l], pA[l + 4]);
    pA[0] = __fadd_rn(pA[0], pA[2]); pA[1] = __fadd_rn(pA[1], pA[3]);
    g_xnorm[r] = __fadd_rn(pA[0], pA[1]);
}

// ---------------- main: 2-chain mma.sync GEMM, register-prefetched B -------
__global__ void __launch_bounds__(NTH, 2) vq_main_mma(const float* __restrict__ x,
                                                      const float* __restrict__ w,
                                                      float* __restrict__ out) {
    extern __shared__ char smem[];
    u32 sb = smem_u32(smem);
    int tid = threadIdx.x, wid = tid >> 5, lane = tid & 31;
    int cta = blockIdx.x;                       // 1024 CTAs
    int b = cta >> 6, t0 = (cta & 63) * ROWS;
    int rowg = wid & 3, nhalf = wid >> 2;

    // issue B prefetch for pass 0 first (latency overlaps A-load below)
    const uint4* bsrc = (const uint4*)g_whi;    // 2048 uint4 per 64-code pass
    uint4 breg[8];
    #pragma unroll
    for (int i = 0; i < 8; i++) breg[i] = __ldg(&bsrc[tid + i * 256]);

    float* wn = (float*)(smem + SM_WN);
    #pragma unroll
    for (int i = tid; i < KK; i += NTH) wn[i] = g_wnorm[i];

    // load + convert + store A (x tile, 64 rows x 256 d), bf16 hi/lo
    {
        const float* xb = x + (size_t)b * DD * TT + t0;
        int r = tid & 63, grp = tid >> 6;       // coalesced on r
        #pragma unroll 4
        for (int it = 0; it < 32; it++) {
            int d = grp * 64 + it * 2;
            float v0 = __ldg(&xb[(size_t)d * TT + r]);
            float v1 = __ldg(&xb[(size_t)(d + 1) * TT + r]);
            __nv_bfloat16 h0 = __float2bfloat16(v0);
            __nv_bfloat16 h1 = __float2bfloat16(v1);
            __nv_bfloat16 l0 = __float2bfloat16(__fadd_rn(v0, -__bfloat162float(h0)));
            __nv_bfloat16 l1 = __float2bfloat16(__fadd_rn(v1, -__bfloat162float(h1)));
            u32 hp = (u32)__bfloat16_as_ushort(h0) | ((u32)__bfloat16_as_ushort(h1) << 16);
            u32 lp = (u32)__bfloat16_as_ushort(l0) | ((u32)__bfloat16_as_ushort(l1) << 16);
            u32 byte = (u32)(r * RSTR + d * 2);
            *(u32*)(smem + SM_A_HI + byte) = hp;
            *(u32*)(smem + SM_A_LO + byte) = lp;
        }
    }

    int g = lane >> 2, q = lane & 3;
    int rl0 = rowg * 16 + g, rl1 = rl0 + 8;     // local rows in [0,64)
    float xn0 = g_xnorm[(size_t)b * TT + t0 + rl0];
    float xn1 = g_xnorm[(size_t)b * TT + t0 + rl1];
    float bs0 = INFINITY, ss0 = INFINITY, bs1 = INFINITY, ss1 = INFINITY;
    int bi0 = 0, bi1 = 0;

    u32 aHi = sb + SM_A_HI + (u32)((rowg * 16 + (lane & 15)) * RSTR + (lane >> 4) * 16);
    u32 aLo = aHi + (SM_A_LO - SM_A_HI);
    u32 bBase = sb + SM_B
              + (u32)((nhalf * 32 + (lane >> 4) * 8 + (lane & 7)) * RSTR)
              + (u32)(((lane >> 3) & 1) * 16);

    for (int pass = 0; pass < NPASS; pass++) {
        __syncthreads();   // prev pass's ldmatrix done (first iter: A-stores visible)
        #pragma unroll
        for (int i = 0; i < 8; i++) {
            int idx = tid + i * 256;
            *(uint4*)(smem + SM_B + (idx >> 5) * RSTR + (idx & 31) * 16) = breg[i];
        }
        __syncthreads();
        if (pass + 1 < NPASS) {   // prefetch next pass into registers (hides under MMA)
            #pragma unroll
            for (int i = 0; i < 8; i++)
                breg[i] = __ldg(&bsrc[(size_t)(pass + 1) * 2048 + tid + i * 256]);
        }

        float acc[4][4];
        #pragma unroll
        for (int nt = 0; nt < 4; nt++)
            #pragma unroll
            for (int c = 0; c < 4; c++) acc[nt][c] = 0.f;

        #pragma unroll 4
        for (int ks = 0; ks < KSTEPS; ks++) {
            u32 ah0, ah1, ah2, ah3, al0, al1, al2, al3;
            ldsm4(ah0, ah1, ah2, ah3, aHi + ks * 32);
            ldsm4(al0, al1, al2, al3, aLo + ks * 32);
            #pragma unroll
            for (int ntp = 0; ntp < 2; ntp++) {
                u32 b0, b1, b2, b3;
                ldsm4(b0, b1, b2, b3, bBase + (u32)(ntp * 16 * RSTR) + ks * 32);
                mma_bf16(acc[ntp * 2],     ah0, ah1, ah2, ah3, b0, b1);
                mma_bf16(acc[ntp * 2],     al0, al1, al2, al3, b0, b1);
                mma_bf16(acc[ntp * 2 + 1], ah0, ah1, ah2, ah3, b2, b3);
                mma_bf16(acc[ntp * 2 + 1], al0, al1, al2, al3, b2, b3);
            }
        }
        // epilogue: dist = fl(fl(xn+wn) - 2*dot), best/second-best, ascending j
        int kb = pass * NCHUNK + nhalf * 32;
        #pragma unroll
        for (int nt = 0; nt < 4; nt++) {
            int j = kb + nt * 8 + q * 2;
            float w0 = wn[j], w1 = wn[j + 1];
            upd(__fmaf_rn(-2.f, acc[nt][0], __fadd_rn(xn0, w0)), j,     bs0, bi0, ss0);
            upd(__fmaf_rn(-2.f, acc[nt][1], __fadd_rn(xn0, w1)), j + 1, bs0, bi0, ss0);
            upd(__fmaf_rn(-2.f, acc[nt][2], __fadd_rn(xn1, w0)), j,     bs1, bi1, ss1);
            upd(__fmaf_rn(-2.f, acc[nt][3], __fadd_rn(xn1, w1)), j + 1, bs1, bi1, ss1);
        }
    }

    // quad reduce (lanes sharing the same rows), then cross-half merge via smem
    qmerge(bs0, bi0, ss0, 1); qmerge(bs0, bi0, ss0, 2);
    qmerge(bs1, bi1, ss1, 1); qmerge(bs1, bi1, ss1, 2);
    float (*mS)[2]  = (float(*)[2])(smem + SM_MS);
    int   (*mI)[2]  = (int(*)[2])(smem + SM_MI);
    float (*mSS)[2] = (float(*)[2])(smem + SM_MSS);
    int* idxs = (int*)(smem + SM_IDX);
    float* rbuf = (float*)(smem + SM_RBUF);
    if (q == 0) {
        mS[rl0][nhalf] = bs0; mI[rl0][nhalf] = bi0; mSS[rl0][nhalf] = ss0;
        mS[rl1][nhalf] = bs1; mI[rl1][nhalf] = bi1; mSS[rl1][nhalf] = ss1;
    }
    __syncthreads();

    float part = 0.f;
    if (tid < ROWS) {
        float bA = mS[tid][0], bB = mS[tid][1], sA = mSS[tid][0], sB = mSS[tid][1];
        int iA = mI[tid][0], iB = mI[tid][1];
        float bs; int bi; float ss;
        if (bB < bA || (bB == bA && iB < iA)) { bs = bB; bi = iB; ss = fminf(bA, sB); }
        else                                  { bs = bA; bi = iA; ss = fminf(sA, bB); }
        int grow = b * TT + t0 + tid;
        g_bestI[grow] = bi;
        idxs[tid] = bi;
        atomicAdd(&g_counts[bi], 1);
        out[OUT_IDX + (size_t)grow] = (float)bi;
        if (ss < bs + MARGIN) { int p = atomicAdd(&g_namb, 1); g_amb[p] = grow; }
        part = bs;
    }
    #pragma unroll
    for (int o = 16; o; o >>= 1) part += __shfl_xor_sync(0xffffffffu, part, o);
    if (lane == 0) rbuf[wid] = part;
    __syncthreads();
    if (tid == 0) {
        float s = 0.f;
        #pragma unroll
        for (int i = 0; i < 8; i++) s += rbuf[i];
        atomicAdd(&g_acc, (double)s);
    }
    // fused gather of quantized output
    #pragma unroll 4
    for (int i = tid; i < ROWS * DD; i += NTH) {
        int r = i >> 8, d = i & 255;
        out[((size_t)(b * TT + t0 + r)) * DD + d] = __ldg(&w[(size_t)idxs[r] * DD + d]);
    }
}

// ---------------- refine v2: 32 rows/block, 4 rows/warp, float4 smem -------
__global__ void __launch_bounds__(256) vq_refine(const float* __restrict__ x,
                                                 const float* __restrict__ w,
                                                 float* __restrict__ out) {
    extern __shared__ float rsm[];
    float* xs   = rsm;                    // [32][RFS]
    float* wch  = rsm + 32 * RFS;         // [32][RFS]
    int* rows_s = (int*)(rsm + 64 * RFS); // [32]
    int tid = threadIdx.x, wid = tid >> 5, lane = tid & 31;
    int namb = g_namb;
    for (int batch = blockIdx.x; batch * 32 < namb; batch += gridDim.x) {
        __syncthreads();
        if (tid < 32) {
            int ai = batch * 32 + tid;
            rows_s[tid] = (ai < namb) ? g_amb[ai] : -1;
        }
        __syncthreads();
        // stage x rows (4 per warp)
        #pragma unroll
        for (int rr = wid; rr < 32; rr += 8) {
            int row = rows_s[rr];
            if (row >= 0) {
                int b = row >> 12, t = row & 4095;
                for (int d = lane; d < 256; d += 32)
                    xs[rr * RFS + d] = __ldg(&x[(size_t)b * DD * TT + (size_t)d * TT + t]);
            } else {
                for (int d = lane; d < 256; d += 32) xs[rr * RFS + d] = 0.f;
            }
        }
        int rb = wid * 4;
        int rowA[4]; float xnA[4], best[4]; int bia[4];
        #pragma unroll
        for (int c = 0; c < 4; c++) {
            rowA[c] = rows_s[rb + c];
            xnA[c] = (rowA[c] >= 0) ? g_xnorm[rowA[c]] : 0.f;
            best[c] = INFINITY; bia[c] = 0;
        }
        const float4* x0 = (const float4*)(xs + (rb + 0) * RFS);
        const float4* x1 = (const float4*)(xs + (rb + 1) * RFS);
        const float4* x2 = (const float4*)(xs + (rb + 2) * RFS);
        const float4* x3 = (const float4*)(xs + (rb + 3) * RFS);
        const float4* wv4 = (const float4*)(wch + lane * RFS);
        for (int kt = 0; kt < KK; kt += 32) {
            __syncthreads();   // xs ready (1st iter) / prev compute done
            // stage 32-code w chunk, float4 (2048 uint4, 8 per thread)
            {
                const float4* src = (const float4*)(w + (size_t)kt * 256);
                #pragma unroll
                for (int i = 0; i < 8; i++) {
                    int idx = tid + i * 256;          // row = idx>>6, c4 = idx&63
                    *(float4*)(wch + (idx >> 6) * RFS + (idx & 63) * 4) = __ldg(&src[idx]);
                }
            }
            __syncthreads();
            float a0 = 0.f, a1 = 0.f, a2 = 0.f, a3 = 0.f;
            #pragma unroll 16
            for (int d4 = 0; d4 < 64; d4++) {
                float4 wv = wv4[d4];
                float4 v0 = x0[d4], v1 = x1[d4], v2 = x2[d4], v3 = x3[d4];
                a0 = __fmaf_rn(v0.x, wv.x, a0); a0 = __fmaf_rn(v0.y, wv.y, a0);
                a0 = __fmaf_rn(v0.z, wv.z, a0); a0 = __fmaf_rn(v0.w, wv.w, a0);
                a1 = __fmaf_rn(v1.x, wv.x, a1); a1 = __fmaf_rn(v1.y, wv.y, a1);
                a1 = __fmaf_rn(v1.z, wv.z, a1); a1 = __fmaf_rn(v1.w, wv.w, a1);
                a2 = __fmaf_rn(v2.x, wv.x, a2); a2 = __fmaf_rn(v2.y, wv.y, a2);
                a2 = __fmaf_rn(v2.z, wv.z, a2); a2 = __fmaf_rn(v2.w, wv.w, a2);
                a3 = __fmaf_rn(v3.x, wv.x, a3); a3 = __fmaf_rn(v3.y, wv.y, a3);
                a3 = __fmaf_rn(v3.z, wv.z, a3); a3 = __fmaf_rn(v3.w, wv.w, a3);
            }
            int k = kt + lane;
            float wnk = g_wnorm[k];
            float s0 = __fmaf_rn(-2.f, a0, __fadd_rn(xnA[0], wnk));
            float s1 = __fmaf_rn(-2.f, a1, __fadd_rn(xnA[1], wnk));
            float s2 = __fmaf_rn(-2.f, a2, __fadd_rn(xnA[2], wnk));
            float s3 = __fmaf_rn(-2.f, a3, __fadd_rn(xnA[3], wnk));
            if (s0 < best[0]) { best[0] = s0; bia[0] = k; }   // per-lane ks ascending
            if (s1 < best[1]) { best[1] = s1; bia[1] = k; }
            if (s2 < best[2]) { best[2] = s2; bia[2] = k; }
            if (s3 < best[3]) { best[3] = s3; bia[3] = k; }
        }
        // warp argmin with lowest-index tiebreak per row
        #pragma unroll
        for (int c = 0; c < 4; c++) {
            float bv = best[c]; int bi = bia[c];
            #pragma unroll
            for (int o = 16; o; o >>= 1) {
                float so = __shfl_xor_sync(0xffffffffu, bv, o);
                int   io = __shfl_xor_sync(0xffffffffu, bi, o);
                if (so < bv || (so == bv && io < bi)) { bv = so; bi = io; }
            }
            int row = rowA[c];
            if (row >= 0 && bi != g_bestI[row]) {
                if (lane == 0) {
                    atomicAdd(&g_counts[g_bestI[row]], -1);
                    atomicAdd(&g_counts[bi], 1);
                    out[OUT_IDX + (size_t)row] = (float)bi;
                }
                for (int d = lane; d < 256; d += 32)
                    out[(size_t)row * DD + d] = __ldg(&w[(size_t)bi * DD + d]);
            }
        }
    }
}

// ---------------- finalize: loss + perplexity ----------------
__global__ void vq_final(float* __restrict__ out) {
    __shared__ float sh[32];
    int tid = threadIdx.x;
    float p = (float)g_counts[tid] / (float)NN;
    float t = p * logf(p + 1e-10f);
    #pragma unroll
    for (int o = 16; o; o >>= 1) t += __shfl_xor_sync(0xffffffffu, t, o);
    if ((tid & 31) == 0) sh[tid >> 5] = t;
    __syncthreads();
    if (tid < 32) {
        float v = sh[tid];
        #pragma unroll
        for (int o = 16; o; o >>= 1) v += __shfl_xor_sync(0xffffffffu, v, o);
        if (tid == 0) {
            out[OUT_PERP] = expf(-v);
            out[OUT_LOSS] = (float)(1.25 * g_acc / ((double)NN * (double)DD));
        }
    }
}

extern "C" void kernel_launch(void* const* d_in, const int* in_sizes, int n_in,
                              void* d_out, int out_size) {
    const float* x = (const float*)d_in[0];   // [16, 256, 4096] fp32
    const float* w = (const float*)d_in[1];   // [1024, 256] fp32
    float* out = (float*)d_out;
    cudaFuncSetAttribute(vq_main_mma, cudaFuncAttributeMaxDynamicSharedMemorySize, SM_TOTAL);
    cudaFuncSetAttribute(vq_refine, cudaFuncAttributeMaxDynamicSharedMemorySize, RF_TOTAL);
    vq_prep<<<(KK * 32) / NTH, NTH>>>(w);              // wnorm + bf16 codebook + zero
    vq_xnorm<<<NN / 256, 256>>>(x);                    // per-row ||x||^2 (order A)
    vq_main_mma<<<NN / ROWS, NTH, SM_TOTAL>>>(x, w, out);  // 1024 CTAs, fused output
    vq_refine<<<1024, 256, RF_TOTAL>>>(x, w, out);     // exact re-scan + patch
    vq_final<<<1, KK>>>(out);
}

// round 17
// speedup vs baseline: 1.1873x; 1.1873x over previous
#include <cuda_runtime.h>
#include <cuda_bf16.h>
#include <math.h>

#define BB 16
#define DD 256
#define TT 4096
#define NN (BB*TT)      // 65536 rows
#define KK 1024         // codes
#define ROWS 64         // rows per CTA
#define NTH 256
#define NCHUNK 64       // codes per pass
#define NPASS (KK/NCHUNK)   // 16
#define KSTEPS (DD/16)  // 16
#define MARGIN 1.5e-4f

#define OUT_LOSS ((size_t)NN*DD)
#define OUT_PERP (OUT_LOSS+1)
#define OUT_IDX  (OUT_PERP+1)

// padded smem row: 256 bf16 + 8 pad = 528 B (132 words; 132%32=4 -> conflict-free ldmatrix)
#define RSTR 528
#define SM_WN    0                      // 1024 floats
#define SM_A_HI  4096                   // 64*528 = 33792
#define SM_A_LO  (SM_A_HI + 33792)      // 37888
#define SM_B     (SM_A_LO + 33792)      // 71680: 64*528 = 33792
#define SM_MS    (SM_B + 33792)         // 105472: float[64][2]
#define SM_MI    (SM_MS + 512)
#define SM_MSS   (SM_MI + 512)
#define SM_IDX   (SM_MSS + 512)         // int[64]
#define SM_RBUF  (SM_IDX + 256)         // float[8]
#define SM_TOTAL (SM_RBUF + 32)         // 107296

// refine smem: stride 260 floats (1040 B, 16B-aligned, LDS.128 conflict-free)
#define RFS 260
#define RF_TOTAL (16 * RFS * 4 + 32 * RFS * 4 + 64)   // xs[16][260] + wch[32][260] + rows[16]

typedef unsigned int u32;
typedef unsigned long long u64;

__device__ float  g_wnorm[KK];
__device__ float  g_xnorm[NN];
__device__ int    g_counts[KK];
__device__ double g_acc;
__device__ int    g_bestI[NN];
__device__ int    g_amb[NN];
__device__ int    g_namb;
__device__ u64    g_pack[NN];              // packed (score,k) for flagged rows
__device__ __nv_bfloat16 g_whi[KK * DD];   // plain [k][d]

__device__ __forceinline__ u32 smem_u32(const void* p) {
    u32 a; asm("{ .reg .u64 t; cvta.to.shared.u64 t, %1; cvt.u32.u64 %0, t; }" : "=r"(a) : "l"(p));
    return a;
}
__device__ __forceinline__ void ldsm4(u32& r0, u32& r1, u32& r2, u32& r3, u32 addr) {
    asm volatile("ldmatrix.sync.aligned.m8n8.x4.shared.b16 {%0,%1,%2,%3}, [%4];"
        : "=r"(r0), "=r"(r1), "=r"(r2), "=r"(r3) : "r"(addr));
}
__device__ __forceinline__ void mma_bf16(float* c, u32 a0, u32 a1, u32 a2, u32 a3, u32 b0, u32 b1) {
    asm volatile("mma.sync.aligned.m16n8k16.row.col.f32.bf16.bf16.f32 "
        "{%0,%1,%2,%3}, {%4,%5,%6,%7}, {%8,%9}, {%0,%1,%2,%3};"
        : "+f"(c[0]), "+f"(c[1]), "+f"(c[2]), "+f"(c[3])
        : "r"(a0), "r"(a1), "r"(a2), "r"(a3), "r"(b0), "r"(b1));
}
__device__ __forceinline__ void upd(float s, int j, float& bs, int& bi, float& ss) {
    if (s < bs) { ss = bs; bs = s; bi = j; }
    else if (s < ss) ss = s;
}
__device__ __forceinline__ void qmerge(float& bs, int& bi, float& ss, int m) {
    float obs = __shfl_xor_sync(0xffffffffu, bs, m);
    int   obi = __shfl_xor_sync(0xffffffffu, bi, m);
    float oss = __shfl_xor_sync(0xffffffffu, ss, m);
    if (obs < bs || (obs == bs && obi < bi)) { ss = fminf(bs, oss); bs = obs; bi = obi; }
    else ss = fminf(ss, fminf(obs, oss));
}
// monotone float->u32 (total order), then lexicographic (score, k)
__device__ __forceinline__ u64 packkey(float s, int k) {
    u32 u = __float_as_uint(s);
    u = (u & 0x80000000u) ? ~u : (u | 0x80000000u);
    return ((u64)u << 32) | (u32)k;
}

// ---------------- prep (fused): wnorm + bf16 codebook + zero scratch -------
__global__ __launch_bounds__(256) void vq_prep(const float* __restrict__ w) {
    int gt   = blockIdx.x * blockDim.x + threadIdx.x;
    int k    = gt >> 5, lane = gt & 31;            // warp per code, 128 blocks
    const float4* wr = (const float4*)(w + (size_t)k * DD);
    float4 v0 = __ldg(&wr[lane]);                  // 64 float4 per row: lane, lane+32
    float4 v1 = __ldg(&wr[lane + 32]);
    float s = 0.f;
    s = __fmaf_rn(v0.x, v0.x, s); s = __fmaf_rn(v0.y, v0.y, s);
    s = __fmaf_rn(v0.z, v0.z, s); s = __fmaf_rn(v0.w, v0.w, s);
    s = __fmaf_rn(v1.x, v1.x, s); s = __fmaf_rn(v1.y, v1.y, s);
    s = __fmaf_rn(v1.z, v1.z, s); s = __fmaf_rn(v1.w, v1.w, s);
    #pragma unroll
    for (int o = 16; o; o >>= 1) s = __fadd_rn(s, __shfl_xor_sync(0xffffffffu, s, o));
    if (lane == 0) g_wnorm[k] = s;
    u32 p0 = (u32)__bfloat16_as_ushort(__float2bfloat16(v0.x))
           | ((u32)__bfloat16_as_ushort(__float2bfloat16(v0.y)) << 16);
    u32 p1 = (u32)__bfloat16_as_ushort(__float2bfloat16(v0.z))
           | ((u32)__bfloat16_as_ushort(__float2bfloat16(v0.w)) << 16);
    u32 p2 = (u32)__bfloat16_as_ushort(__float2bfloat16(v1.x))
           | ((u32)__bfloat16_as_ushort(__float2bfloat16(v1.y)) << 16);
    u32 p3 = (u32)__bfloat16_as_ushort(__float2bfloat16(v1.z))
           | ((u32)__bfloat16_as_ushort(__float2bfloat16(v1.w)) << 16);
    uint2* dst = (uint2*)g_whi;
    dst[(size_t)k * 64 + lane]      = make_uint2(p0, p1);
    dst[(size_t)k * 64 + lane + 32] = make_uint2(p2, p3);
    if (gt < KK) g_counts[gt] = 0;
    if (gt == 0) { g_acc = 0.0; g_namb = 0; }
}

// ---------------- xnorm: per-row sum(x^2), GPU warp-reduce order ----------
__global__ __launch_bounds__(256) void vq_xnorm(const float* __restrict__ x) {
    int r = blockIdx.x * blockDim.x + threadIdx.x;
    int b = r >> 12, t = r & 4095;
    const float* xp = x + (size_t)b * (DD * TT) + t;
    float pA[32];
    #pragma unroll
    for (int l = 0; l < 32; l++) pA[l] = 0.f;
    #pragma unroll 1
    for (int i = 0; i < 8; i++) {
        #pragma unroll
        for (int l = 0; l < 32; l++) {
            float v = __ldg(&xp[(size_t)(i * 32 + l) * TT]);
            pA[l] = __fadd_rn(pA[l], __fmul_rn(v, v));
        }
    }
    #pragma unroll
    for (int l = 0; l < 16; l++) pA[l] = __fadd_rn(pA[l], pA[l + 16]);
    #pragma unroll
    for (int l = 0; l < 8; l++)  pA[l] = __fadd_rn(pA[l], pA[l + 8]);
    #pragma unroll
    for (int l = 0; l < 4; l++)  pA[l] = __fadd_rn(pA[l], pA[l + 4]);
    pA[0] = __fadd_rn(pA[0], pA[2]); pA[1] = __fadd_rn(pA[1], pA[3]);
    g_xnorm[r] = __fadd_rn(pA[0], pA[1]);
}

// ---------------- main: 2-chain mma.sync GEMM, register-prefetched B -------
__global__ void __launch_bounds__(NTH, 2) vq_main_mma(const float* __restrict__ x,
                                                      const float* __restrict__ w,
                                                      float* __restrict__ out) {
    extern __shared__ char smem[];
    u32 sb = smem_u32(smem);
    int tid = threadIdx.x, wid = tid >> 5, lane = tid & 31;
    int cta = blockIdx.x;                       // 1024 CTAs
    int b = cta >> 6, t0 = (cta & 63) * ROWS;
    int rowg = wid & 3, nhalf = wid >> 2;

    // issue B prefetch for pass 0 first (latency overlaps A-load below)
    const uint4* bsrc = (const uint4*)g_whi;    // 2048 uint4 per 64-code pass
    uint4 breg[8];
    #pragma unroll
    for (int i = 0; i < 8; i++) breg[i] = __ldg(&bsrc[tid + i * 256]);

    float* wn = (float*)(smem + SM_WN);
    #pragma unroll
    for (int i = tid; i < KK; i += NTH) wn[i] = g_wnorm[i];

    // load + convert + store A (x tile, 64 rows x 256 d), bf16 hi/lo
    {
        const float* xb = x + (size_t)b * DD * TT + t0;
        int r = tid & 63, grp = tid >> 6;       // coalesced on r
        #pragma unroll 4
        for (int it = 0; it < 32; it++) {
            int d = grp * 64 + it * 2;
            float v0 = __ldg(&xb[(size_t)d * TT + r]);
            float v1 = __ldg(&xb[(size_t)(d + 1) * TT + r]);
            __nv_bfloat16 h0 = __float2bfloat16(v0);
            __nv_bfloat16 h1 = __float2bfloat16(v1);
            __nv_bfloat16 l0 = __float2bfloat16(__fadd_rn(v0, -__bfloat162float(h0)));
            __nv_bfloat16 l1 = __float2bfloat16(__fadd_rn(v1, -__bfloat162float(h1)));
            u32 hp = (u32)__bfloat16_as_ushort(h0) | ((u32)__bfloat16_as_ushort(h1) << 16);
            u32 lp = (u32)__bfloat16_as_ushort(l0) | ((u32)__bfloat16_as_ushort(l1) << 16);
            u32 byte = (u32)(r * RSTR + d * 2);
            *(u32*)(smem + SM_A_HI + byte) = hp;
            *(u32*)(smem + SM_A_LO + byte) = lp;
        }
    }

    int g = lane >> 2, q = lane & 3;
    int rl0 = rowg * 16 + g, rl1 = rl0 + 8;     // local rows in [0,64)
    float xn0 = g_xnorm[(size_t)b * TT + t0 + rl0];
    float xn1 = g_xnorm[(size_t)b * TT + t0 + rl1];
    float bs0 = INFINITY, ss0 = INFINITY, bs1 = INFINITY, ss1 = INFINITY;
    int bi0 = 0, bi1 = 0;

    u32 aHi = sb + SM_A_HI + (u32)((rowg * 16 + (lane & 15)) * RSTR + (lane >> 4) * 16);
    u32 aLo = aHi + (SM_A_LO - SM_A_HI);
    u32 bBase = sb + SM_B
              + (u32)((nhalf * 32 + (lane >> 4) * 8 + (lane & 7)) * RSTR)
              + (u32)(((lane >> 3) & 1) * 16);

    for (int pass = 0; pass < NPASS; pass++) {
        __syncthreads();   // prev pass's ldmatrix done (first iter: A-stores visible)
        #pragma unroll
        for (int i = 0; i < 8; i++) {
            int idx = tid + i * 256;
            *(uint4*)(smem + SM_B + (idx >> 5) * RSTR + (idx & 31) * 16) = breg[i];
        }
        __syncthreads();
        if (pass + 1 < NPASS) {   // prefetch next pass into registers (hides under MMA)
            #pragma unroll
            for (int i = 0; i < 8; i++)
                breg[i] = __ldg(&bsrc[(size_t)(pass + 1) * 2048 + tid + i * 256]);
        }

        float acc[4][4];
        #pragma unroll
        for (int nt = 0; nt < 4; nt++)
            #pragma unroll
            for (int c = 0; c < 4; c++) acc[nt][c] = 0.f;

        #pragma unroll 4
        for (int ks = 0; ks < KSTEPS; ks++) {
            u32 ah0, ah1, ah2, ah3, al0, al1, al2, al3;
            ldsm4(ah0, ah1, ah2, ah3, aHi + ks * 32);
            ldsm4(al0, al1, al2, al3, aLo + ks * 32);
            #pragma unroll
            for (int ntp = 0; ntp < 2; ntp++) {
                u32 b0, b1, b2, b3;
                ldsm4(b0, b1, b2, b3, bBase + (u32)(ntp * 16 * RSTR) + ks * 32);
                mma_bf16(acc[ntp * 2],     ah0, ah1, ah2, ah3, b0, b1);
                mma_bf16(acc[ntp * 2],     al0, al1, al2, al3, b0, b1);
                mma_bf16(acc[ntp * 2 + 1], ah0, ah1, ah2, ah3, b2, b3);
                mma_bf16(acc[ntp * 2 + 1], al0, al1, al2, al3, b2, b3);
            }
        }
        // epilogue: dist = fl(fl(xn+wn) - 2*dot), best/second-best, ascending j
        int kb = pass * NCHUNK + nhalf * 32;
        #pragma unroll
        for (int nt = 0; nt < 4; nt++) {
            int j = kb + nt * 8 + q * 2;
            float w0 = wn[j], w1 = wn[j + 1];
            upd(__fmaf_rn(-2.f, acc[nt][0], __fadd_rn(xn0, w0)), j,     bs0, bi0, ss0);
            upd(__fmaf_rn(-2.f, acc[nt][1], __fadd_rn(xn0, w1)), j + 1, bs0, bi0, ss0);
            upd(__fmaf_rn(-2.f, acc[nt][2], __fadd_rn(xn1, w0)), j,     bs1, bi1, ss1);
            upd(__fmaf_rn(-2.f, acc[nt][3], __fadd_rn(xn1, w1)), j + 1, bs1, bi1, ss1);
        }
    }

    // quad reduce (lanes sharing the same rows), then cross-half merge via smem
    qmerge(bs0, bi0, ss0, 1); qmerge(bs0, bi0, ss0, 2);
    qmerge(bs1, bi1, ss1, 1); qmerge(bs1, bi1, ss1, 2);
    float (*mS)[2]  = (float(*)[2])(smem + SM_MS);
    int   (*mI)[2]  = (int(*)[2])(smem + SM_MI);
    float (*mSS)[2] = (float(*)[2])(smem + SM_MSS);
    int* idxs = (int*)(smem + SM_IDX);
    float* rbuf = (float*)(smem + SM_RBUF);
    if (q == 0) {
        mS[rl0][nhalf] = bs0; mI[rl0][nhalf] = bi0; mSS[rl0][nhalf] = ss0;
        mS[rl1][nhalf] = bs1; mI[rl1][nhalf] = bi1; mSS[rl1][nhalf] = ss1;
    }
    __syncthreads();

    float part = 0.f;
    if (tid < ROWS) {
        float bA = mS[tid][0], bB = mS[tid][1], sA = mSS[tid][0], sB = mSS[tid][1];
        int iA = mI[tid][0], iB = mI[tid][1];
        float bs; int bi; float ss;
        if (bB < bA || (bB == bA && iB < iA)) { bs = bB; bi = iB; ss = fminf(bA, sB); }
        else                                  { bs = bA; bi = iA; ss = fminf(sA, bB); }
        int grow = b * TT + t0 + tid;
        g_bestI[grow] = bi;
        idxs[tid] = bi;
        atomicAdd(&g_counts[bi], 1);
        out[OUT_IDX + (size_t)grow] = (float)bi;
        if (ss < bs + MARGIN) {
            int p = atomicAdd(&g_namb, 1);
            g_amb[p] = grow;
            g_pack[grow] = ~0ull;          // refine mins into this
        }
        part = bs;
    }
    #pragma unroll
    for (int o = 16; o; o >>= 1) part += __shfl_xor_sync(0xffffffffu, part, o);
    if (lane == 0) rbuf[wid] = part;
    __syncthreads();
    if (tid == 0) {
        float s = 0.f;
        #pragma unroll
        for (int i = 0; i < 8; i++) s += rbuf[i];
        atomicAdd(&g_acc, (double)s);
    }
    // fused gather of quantized output
    #pragma unroll 4
    for (int i = tid; i < ROWS * DD; i += NTH) {
        int r = i >> 8, d = i & 255;
        out[((size_t)(b * TT + t0 + r)) * DD + d] = __ldg(&w[(size_t)idxs[r] * DD + d]);
    }
}

// ------- refine v3: work item = (16-row group) x (128-code split) ----------
// Exact per-(row,code) scoring, identical arithmetic chain; cross-block merge
// via atomicMin on packed (monotone(score), k) -> reference argmin + tiebreak.
__global__ void __launch_bounds__(256) vq_refine(const float* __restrict__ x,
                                                 const float* __restrict__ w) {
    extern __shared__ float rsm[];
    float* xs   = rsm;                    // [16][RFS]
    float* wch  = rsm + 16 * RFS;         // [32][RFS]
    int* rows_s = (int*)(rsm + 48 * RFS); // [16]
    int tid = threadIdx.x, wid = tid >> 5, lane = tid & 31;
    int namb = g_namb;
    int ngrp = (namb + 15) >> 4;
    int nitems = ngrp * 8;                // 8 code-splits of 128
    for (int item = blockIdx.x; item < nitems; item += gridDim.x) {
        int rg = item >> 3, sp = item & 7;
        __syncthreads();
        if (tid < 16) {
            int ai = rg * 16 + tid;
            rows_s[tid] = (ai < namb) ? g_amb[ai] : -1;
        }
        __syncthreads();
        // stage 16 x rows (2 per warp)
        #pragma unroll
        for (int rr = wid; rr < 16; rr += 8) {
            int row = rows_s[rr];
            if (row >= 0) {
                int b = row >> 12, t = row & 4095;
                for (int d = lane; d < 256; d += 32)
                    xs[rr * RFS + d] = __ldg(&x[(size_t)b * DD * TT + (size_t)d * TT + t]);
            } else {
                for (int d = lane; d < 256; d += 32) xs[rr * RFS + d] = 0.f;
            }
        }
        int r0 = wid * 2, r1 = r0 + 1;    // this warp's 2 rows
        int row0 = rows_s[r0], row1 = rows_s[r1];
        float xn0 = (row0 >= 0) ? g_xnorm[row0] : 0.f;
        float xn1 = (row1 >= 0) ? g_xnorm[row1] : 0.f;
        u64 key0 = ~0ull, key1 = ~0ull;
        const float4* x0 = (const float4*)(xs + r0 * RFS);
        const float4* x1 = (const float4*)(xs + r1 * RFS);
        const float4* wv4 = (const float4*)(wch + lane * RFS);
        for (int ch = 0; ch < 4; ch++) {  // 4 chunks of 32 codes = 128 codes
            int kt = sp * 128 + ch * 32;
            __syncthreads();
            {   // stage 32-code w chunk as float4
                const float4* src = (const float4*)(w + (size_t)kt * 256);
                #pragma unroll
                for (int i = 0; i < 8; i++) {
                    int idx = tid + i * 256;          // row = idx>>6, c4 = idx&63
                    *(float4*)(wch + (idx >> 6) * RFS + (idx & 63) * 4) = __ldg(&src[idx]);
                }
            }
            __syncthreads();
            float a0 = 0.f, a1 = 0.f;
            #pragma unroll 16
            for (int d4 = 0; d4 < 64; d4++) {
                float4 wv = wv4[d4];
                float4 v0 = x0[d4], v1 = x1[d4];
                a0 = __fmaf_rn(v0.x, wv.x, a0); a0 = __fmaf_rn(v0.y, wv.y, a0);
                a0 = __fmaf_rn(v0.z, wv.z, a0); a0 = __fmaf_rn(v0.w, wv.w, a0);
                a1 = __fmaf_rn(v1.x, wv.x, a1); a1 = __fmaf_rn(v1.y, wv.y, a1);
                a1 = __fmaf_rn(v1.z, wv.z, a1); a1 = __fmaf_rn(v1.w, wv.w, a1);
            }
            int k = kt + lane;
            float wnk = g_wnorm[k];
            float s0 = __fmaf_rn(-2.f, a0, __fadd_rn(xn0, wnk));
            float s1 = __fmaf_rn(-2.f, a1, __fadd_rn(xn1, wnk));
            u64 k0 = packkey(s0, k), k1 = packkey(s1, k);
            if (k0 < key0) key0 = k0;
            if (k1 < key1) key1 = k1;
        }
        // warp-reduce packed min, one atomic per (row, split)
        #pragma unroll
        for (int o = 16; o; o >>= 1) {
            u64 o0 = __shfl_xor_sync(0xffffffffu, key0, o);
            u64 o1 = __shfl_xor_sync(0xffffffffu, key1, o);
            if (o0 < key0) key0 = o0;
            if (o1 < key1) key1 = o1;
        }
        if (lane == 0) {
            if (row0 >= 0) atomicMin(&g_pack[row0], key0);
            if (row1 >= 0) atomicMin(&g_pack[row1], key1);
        }
    }
}

// ------- patch: apply refined argmin (counts, idx, gather) -----------------
__global__ void __launch_bounds__(256) vq_patch(const float* __restrict__ w,
                                                float* __restrict__ out) {
    int wid_g = (blockIdx.x * 256 + threadIdx.x) >> 5;   // global warp id
    int lane = threadIdx.x & 31;
    int nwarps = gridDim.x * 8;
    int namb = g_namb;
    for (int i = wid_g; i < namb; i += nwarps) {
        int row = g_amb[i];
        int bi = (int)(u32)g_pack[row];
        if (bi != g_bestI[row]) {
            if (lane == 0) {
                atomicAdd(&g_counts[g_bestI[row]], -1);
                atomicAdd(&g_counts[bi], 1);
                out[OUT_IDX + (size_t)row] = (float)bi;
            }
            for (int d = lane; d < 256; d += 32)
                out[(size_t)row * DD + d] = __ldg(&w[(size_t)bi * DD + d]);
        }
    }
}

// ---------------- finalize: loss + perplexity ----------------
__global__ void vq_final(float* __restrict__ out) {
    __shared__ float sh[32];
    int tid = threadIdx.x;
    float p = (float)g_counts[tid] / (float)NN;
    float t = p * logf(p + 1e-10f);
    #pragma unroll
    for (int o = 16; o; o >>= 1) t += __shfl_xor_sync(0xffffffffu, t, o);
    if ((tid & 31) == 0) sh[tid >> 5] = t;
    __syncthreads();
    if (tid < 32) {
        float v = sh[tid];
        #pragma unroll
        for (int o = 16; o; o >>= 1) v += __shfl_xor_sync(0xffffffffu, v, o);
        if (tid == 0) {
            out[OUT_PERP] = expf(-v);
            out[OUT_LOSS] = (float)(1.25 * g_acc / ((double)NN * (double)DD));
        }
    }
}

extern "C" void kernel_launch(void* const* d_in, const int* in_sizes, int n_in,
                              void* d_out, int out_size) {
    const float* x = (const float*)d_in[0];   // [16, 256, 4096] fp32
    const float* w = (const float*)d_in[1];   // [1024, 256] fp32
    float* out = (float*)d_out;
    cudaFuncSetAttribute(vq_main_mma, cudaFuncAttributeMaxDynamicSharedMemorySize, SM_TOTAL);
    cudaFuncSetAttribute(vq_refine, cudaFuncAttributeMaxDynamicSharedMemorySize, RF_TOTAL);
    vq_prep<<<(KK * 32) / NTH, NTH>>>(w);              // wnorm + bf16 codebook + zero
    vq_xnorm<<<NN / 256, 256>>>(x);                    // per-row ||x||^2 (order A)
    vq_main_mma<<<NN / ROWS, NTH, SM_TOTAL>>>(x, w, out);  // 1024 CTAs, fused output
    vq_refine<<<1024, 256, RF_TOTAL>>>(x, w);          // exact split re-scan
    vq_patch<<<128, 256>>>(w, out);                    // apply changed rows
    vq_final<<<1, KK>>>(out);
}